// round 11
// baseline (speedup 1.0000x reference)
#include <cuda_runtime.h>
#include <cuda_fp16.h>
#include <math.h>
#include <stdint.h>

// Problem constants (fixed by the reference)
#define Hh    256
#define ISZ   512
#define SSZ   16
#define RSZ   16
#define KC    4
#define NLAY  8
#define BATCH 16
#define LSEQ  2048
#define MROWS (BATCH * LSEQ)      // 32768
#define NSSM  (RSZ + 2 * SSZ)     // 48

// -------------------- static scratch (no allocations allowed) --------------------
__device__ __align__(256) float g_scratch[(size_t)MROWS * 2864];

#define OFF_H    ((size_t)0)
#define OFF_PROJ ((size_t)MROWS * Hh)
#define OFF_U    (OFF_PROJ + (size_t)MROWS * 2 * ISZ)
#define OFF_SSM  (OFF_U + (size_t)MROWS * ISZ)
#define OFF_DT   (OFF_SSM + (size_t)MROWS * NSSM)
#define OFF_Y    (OFF_DT + (size_t)MROWS * ISZ)

// -------------------- RMSNorm: one warp per row of 256 --------------------
__global__ void __launch_bounds__(256) rmsnorm_kernel(
    const float* __restrict__ x, const float* __restrict__ w,
    float* __restrict__ out)
{
    int warp = (blockIdx.x * blockDim.x + threadIdx.x) >> 5;
    int lane = threadIdx.x & 31;
    if (warp >= MROWS) return;
    const float4* xr = (const float4*)(x + (size_t)warp * Hh);
    float4 v0 = xr[lane * 2 + 0];
    float4 v1 = xr[lane * 2 + 1];
    float ss = v0.x * v0.x + v0.y * v0.y + v0.z * v0.z + v0.w * v0.w
             + v1.x * v1.x + v1.y * v1.y + v1.z * v1.z + v1.w * v1.w;
#pragma unroll
    for (int o = 16; o > 0; o >>= 1) ss += __shfl_xor_sync(0xffffffffu, ss, o);
    float sc = rsqrtf(ss * (1.0f / Hh) + 1e-5f);
    const float4* wr = (const float4*)w;
    float4 w0 = wr[lane * 2 + 0];
    float4 w1 = wr[lane * 2 + 1];
    float4 o0 = make_float4(v0.x * sc * w0.x, v0.y * sc * w0.y,
                            v0.z * sc * w0.z, v0.w * sc * w0.w);
    float4 o1 = make_float4(v1.x * sc * w1.x, v1.y * sc * w1.y,
                            v1.z * sc * w1.z, v1.w * sc * w1.w);
    float4* orow = (float4*)(out + (size_t)warp * Hh);
    orow[lane * 2 + 0] = o0;
    orow[lane * 2 + 1] = o1;
}

enum { EPI_NONE = 0, EPI_SOFTPLUS_BIAS = 1, EPI_RESADD = 2 };

// -------------------- fp16 tensor-core GEMM (mma.sync m16n8k16) --------------------
// C[m,n] = sum_k A[m,k] * B[n,k]; A,B fp32 in gmem, converted to fp16 while
// staging into smem. BM=BN=128, BK=32, 256 threads = 4(M) x 2(N) warps,
// warp tile 32x64 = 2 x 8 m16n8k16 fragments, fp32 accumulate.
// Smem: k-major rows of 16 f16x2 words, XOR swizzle (kw ^ 2*(row&7)) ->
// conflict-free fragment loads (verified bank mapping: 8 distinct rows x 4
// words cover all 32 banks; rows r and r+8 share the swizzle constant).

__device__ __forceinline__ uint32_t f2h2(float a, float b) {
    __half2 h = __floats2half2_rn(a, b);
    return *reinterpret_cast<uint32_t*>(&h);
}

__device__ __forceinline__ void mma16816(float* c, const uint32_t* a,
                                         const uint32_t* b) {
    asm volatile(
        "mma.sync.aligned.m16n8k16.row.col.f32.f16.f16.f32 "
        "{%0,%1,%2,%3}, {%4,%5,%6,%7}, {%8,%9}, {%0,%1,%2,%3};\n"
        : "+f"(c[0]), "+f"(c[1]), "+f"(c[2]), "+f"(c[3])
        : "r"(a[0]), "r"(a[1]), "r"(a[2]), "r"(a[3]), "r"(b[0]), "r"(b[1]));
}

template <int EPI>
__global__ void __launch_bounds__(256) hgemm_kernel(
    const float* __restrict__ A, const float* __restrict__ B,
    float* __restrict__ C, int K, int lda, int ldb, int ldc)
{
    __shared__ uint32_t As[2][128][16];
    __shared__ uint32_t Bs[2][128][16];

    int tid = threadIdx.x;
    int m0 = blockIdx.y * 128, n0 = blockIdx.x * 128;
    int warp = tid >> 5, lane = tid & 31;
    int wm = warp & 3, wn = warp >> 2;       // 4 x 2 warp grid
    int grp = lane >> 2, tig = lane & 3;

    // staging lanes: thread -> (row, half of k-range)
    int lrow = tid >> 1;
    int lhalf = tid & 1;
    const float* Ap = A + (size_t)(m0 + lrow) * lda + lhalf * 16;
    const float* Bp = B + (size_t)(n0 + lrow) * ldb + lhalf * 16;
    int ssw = 2 * (lrow & 7);

    float4 ra[4], rb[4];
    float acc[2][8][4];
#pragma unroll
    for (int i = 0; i < 2; i++)
#pragma unroll
        for (int j = 0; j < 8; j++)
#pragma unroll
            for (int q = 0; q < 4; q++) acc[i][j][q] = 0.0f;

#pragma unroll
    for (int i = 0; i < 4; i++) {
        ra[i] = *(const float4*)(Ap + i * 4);
        rb[i] = *(const float4*)(Bp + i * 4);
    }

    int KT = K / 32;
    int buf = 0;
    // stage tile 0
#pragma unroll
    for (int i = 0; i < 4; i++) {
        int kw = lhalf * 8 + i * 2;
        As[0][lrow][kw ^ ssw] = f2h2(ra[i].x, ra[i].y);
        As[0][lrow][(kw + 1) ^ ssw] = f2h2(ra[i].z, ra[i].w);
        Bs[0][lrow][kw ^ ssw] = f2h2(rb[i].x, rb[i].y);
        Bs[0][lrow][(kw + 1) ^ ssw] = f2h2(rb[i].z, rb[i].w);
    }
    __syncthreads();

    for (int kt = 0; kt < KT; kt++) {
        if (kt + 1 < KT) {
#pragma unroll
            for (int i = 0; i < 4; i++) {
                ra[i] = *(const float4*)(Ap + (kt + 1) * 32 + i * 4);
                rb[i] = *(const float4*)(Bp + (kt + 1) * 32 + i * 4);
            }
        }
        // compute on buf
#pragma unroll
        for (int ks = 0; ks < 2; ks++) {
            int kw0 = ks * 8;
            uint32_t af[2][4];
#pragma unroll
            for (int i = 0; i < 2; i++) {
                int r = wm * 32 + i * 16 + grp;
                int sw = 2 * (r & 7);
                af[i][0] = As[buf][r][(kw0 + tig) ^ sw];
                af[i][1] = As[buf][r + 8][(kw0 + tig) ^ sw];
                af[i][2] = As[buf][r][(kw0 + tig + 4) ^ sw];
                af[i][3] = As[buf][r + 8][(kw0 + tig + 4) ^ sw];
            }
            uint32_t bf[8][2];
#pragma unroll
            for (int j = 0; j < 8; j++) {
                int c = wn * 64 + j * 8 + grp;
                int sw = 2 * (c & 7);
                bf[j][0] = Bs[buf][c][(kw0 + tig) ^ sw];
                bf[j][1] = Bs[buf][c][(kw0 + tig + 4) ^ sw];
            }
#pragma unroll
            for (int i = 0; i < 2; i++)
#pragma unroll
                for (int j = 0; j < 8; j++) mma16816(acc[i][j], af[i], bf[j]);
        }
        if (kt + 1 < KT) {
            int nb = buf ^ 1;
#pragma unroll
            for (int i = 0; i < 4; i++) {
                int kw = lhalf * 8 + i * 2;
                As[nb][lrow][kw ^ ssw] = f2h2(ra[i].x, ra[i].y);
                As[nb][lrow][(kw + 1) ^ ssw] = f2h2(ra[i].z, ra[i].w);
                Bs[nb][lrow][kw ^ ssw] = f2h2(rb[i].x, rb[i].y);
                Bs[nb][lrow][(kw + 1) ^ ssw] = f2h2(rb[i].z, rb[i].w);
            }
            __syncthreads();
            buf = nb;
        }
    }

    // epilogue: c0,c1 -> (m, n..n+1); c2,c3 -> (m+8, n..n+1)
#pragma unroll
    for (int i = 0; i < 2; i++) {
        int m = m0 + wm * 32 + i * 16 + grp;
#pragma unroll
        for (int j = 0; j < 8; j++) {
            int n = n0 + wn * 64 + j * 8 + tig * 2;
            float2* p0 = (float2*)(C + (size_t)m * ldc + n);
            float2* p1 = (float2*)(C + (size_t)(m + 8) * ldc + n);
            if (EPI == EPI_RESADD) {
                float2 v0 = *p0, v1 = *p1;
                v0.x += acc[i][j][0]; v0.y += acc[i][j][1];
                v1.x += acc[i][j][2]; v1.y += acc[i][j][3];
                *p0 = v0; *p1 = v1;
            } else {
                *p0 = make_float2(acc[i][j][0], acc[i][j][1]);
                *p1 = make_float2(acc[i][j][2], acc[i][j][3]);
            }
        }
    }
}

// -------------------- 128x128x8 fp32 SGEMM (dt_proj) --------------------
template <int EPI>
__global__ void __launch_bounds__(256) gemm128_kernel(
    const float* __restrict__ A, const float* __restrict__ B,
    float* __restrict__ C, int K, int lda, int ldb, int ldc,
    const float* __restrict__ bias)
{
    __shared__ float As[2][8][132];
    __shared__ float Bs[2][8][132];

    int tid = threadIdx.x;
    int m0 = blockIdx.y * 128;
    int n0 = blockIdx.x * 128;

    int lm = tid >> 1;
    int lk = (tid & 1) * 4;
    const float* Aptr = A + (size_t)(m0 + lm) * lda + lk;
    const float* Bptr = B + (size_t)(n0 + lm) * ldb + lk;

    int tx = tid & 15;
    int ty = tid >> 4;

    float acc[8][8];
#pragma unroll
    for (int i = 0; i < 8; i++)
#pragma unroll
        for (int j = 0; j < 8; j++) acc[i][j] = 0.0f;

    float4 ra = *(const float4*)Aptr;
    float4 rb = *(const float4*)Bptr;

    int KT = K / 8;
    int buf = 0;
    for (int kt = 0; kt < KT; kt++) {
        As[buf][lk + 0][lm] = ra.x;
        As[buf][lk + 1][lm] = ra.y;
        As[buf][lk + 2][lm] = ra.z;
        As[buf][lk + 3][lm] = ra.w;
        Bs[buf][lk + 0][lm] = rb.x;
        Bs[buf][lk + 1][lm] = rb.y;
        Bs[buf][lk + 2][lm] = rb.z;
        Bs[buf][lk + 3][lm] = rb.w;
        __syncthreads();
        if (kt + 1 < KT) {
            ra = *(const float4*)(Aptr + (kt + 1) * 8);
            rb = *(const float4*)(Bptr + (kt + 1) * 8);
        }
#pragma unroll
        for (int k = 0; k < 8; k++) {
            float4 a0 = *(const float4*)&As[buf][k][ty * 8];
            float4 a1 = *(const float4*)&As[buf][k][ty * 8 + 4];
            float4 b0 = *(const float4*)&Bs[buf][k][tx * 8];
            float4 b1 = *(const float4*)&Bs[buf][k][tx * 8 + 4];
            float av[8] = {a0.x, a0.y, a0.z, a0.w, a1.x, a1.y, a1.z, a1.w};
            float bv[8] = {b0.x, b0.y, b0.z, b0.w, b1.x, b1.y, b1.z, b1.w};
#pragma unroll
            for (int i = 0; i < 8; i++)
#pragma unroll
                for (int j = 0; j < 8; j++) acc[i][j] += av[i] * bv[j];
        }
        buf ^= 1;
    }

#pragma unroll
    for (int i = 0; i < 8; i++) {
        int m = m0 + ty * 8 + i;
        float* crow = C + (size_t)m * ldc + n0 + tx * 8;
        if (EPI == EPI_NONE) {
            ((float4*)crow)[0] = make_float4(acc[i][0], acc[i][1], acc[i][2], acc[i][3]);
            ((float4*)crow)[1] = make_float4(acc[i][4], acc[i][5], acc[i][6], acc[i][7]);
        } else if (EPI == EPI_SOFTPLUS_BIAS) {
            float o[8];
#pragma unroll
            for (int j = 0; j < 8; j++) {
                float v = acc[i][j] + bias[n0 + tx * 8 + j];
                o[j] = fmaxf(v, 0.0f) + log1pf(__expf(-fabsf(v)));
            }
            ((float4*)crow)[0] = make_float4(o[0], o[1], o[2], o[3]);
            ((float4*)crow)[1] = make_float4(o[4], o[5], o[6], o[7]);
        } else {
            float4 c0 = ((float4*)crow)[0];
            float4 c1 = ((float4*)crow)[1];
            c0.x += acc[i][0]; c0.y += acc[i][1]; c0.z += acc[i][2]; c0.w += acc[i][3];
            c1.x += acc[i][4]; c1.y += acc[i][5]; c1.z += acc[i][6]; c1.w += acc[i][7];
            ((float4*)crow)[0] = c0;
            ((float4*)crow)[1] = c1;
        }
    }
}

// -------------------- small-N tiled GEMM (x_proj, N=48; fp32 for precision) ----
template <int BM, int BN, int BK, int TM, int TN, int EPI>
__global__ void __launch_bounds__((BM / TM) * (BN / TN)) gemm_kernel(
    const float* __restrict__ A, const float* __restrict__ B,
    float* __restrict__ C, int K, int lda, int ldb, int ldc,
    const float* __restrict__ bias)
{
    constexpr int THREADS = (BM / TM) * (BN / TN);
    constexpr int AE = BM * BK / THREADS;
    constexpr int BE = BN * BK / THREADS;
    static_assert(AE % 4 == 0, "A loader uses float4");

    __shared__ float As[BM * BK];
    __shared__ float Bs[BK * BN];

    int tid = threadIdx.x;
    int tx = tid % (BN / TN);
    int ty = tid / (BN / TN);
    int m0 = blockIdx.y * BM;
    int n0 = blockIdx.x * BN;

    const float* Ab = A + (size_t)m0 * lda;
    const float* Bb = B + (size_t)n0 * ldb;

    float rA[AE];
    float rB[BE];

    auto loadA = [&](int k0) {
#pragma unroll
        for (int j = 0; j < AE; j += 4) {
            int e = tid * AE + j;
            int m = e / BK, k = e % BK;
            float4 v = *(const float4*)(Ab + (size_t)m * lda + k0 + k);
            rA[j] = v.x; rA[j + 1] = v.y; rA[j + 2] = v.z; rA[j + 3] = v.w;
        }
    };
    auto loadB = [&](int k0) {
#pragma unroll
        for (int j = 0; j < BE; j++) {
            int e = tid * BE + j;
            int n = e / BK, k = e % BK;
            rB[j] = Bb[(size_t)n * ldb + k0 + k];
        }
    };

    float acc[TM][TN];
#pragma unroll
    for (int i = 0; i < TM; i++)
#pragma unroll
        for (int j = 0; j < TN; j++) acc[i][j] = 0.0f;

    loadA(0);
    loadB(0);
    int KT = K / BK;
    for (int kt = 0; kt < KT; kt++) {
#pragma unroll
        for (int j = 0; j < AE; j++) As[tid * AE + j] = rA[j];
#pragma unroll
        for (int j = 0; j < BE; j++) {
            int e = tid * BE + j;
            int n = e / BK, k = e % BK;
            Bs[k * BN + n] = rB[j];
        }
        __syncthreads();
        if (kt + 1 < KT) { loadA((kt + 1) * BK); loadB((kt + 1) * BK); }
#pragma unroll
        for (int k = 0; k < BK; k++) {
            float a[TM], bb[TN];
#pragma unroll
            for (int i = 0; i < TM; i++) a[i] = As[(ty * TM + i) * BK + k];
#pragma unroll
            for (int j = 0; j < TN; j++) bb[j] = Bs[k * BN + tx * TN + j];
#pragma unroll
            for (int i = 0; i < TM; i++)
#pragma unroll
                for (int j = 0; j < TN; j++) acc[i][j] += a[i] * bb[j];
        }
        __syncthreads();
    }

#pragma unroll
    for (int i = 0; i < TM; i++) {
        int m = m0 + ty * TM + i;
#pragma unroll
        for (int j = 0; j < TN; j++) {
            int n = n0 + tx * TN + j;
            size_t idx = (size_t)m * ldc + n;
            if (EPI == EPI_NONE) {
                C[idx] = acc[i][j];
            } else if (EPI == EPI_SOFTPLUS_BIAS) {
                float v = acc[i][j] + bias[n];
                C[idx] = fmaxf(v, 0.0f) + log1pf(__expf(-fabsf(v)));
            } else {
                C[idx] += acc[i][j];
            }
        }
    }
}

// -------------------- depthwise causal conv (K=4) + bias + SiLU (float4) ------
// Each thread handles 4 consecutive channels of one (b,l) row.
__global__ void __launch_bounds__(256) conv_silu_kernel(
    const float* __restrict__ proj, const float* __restrict__ cw,
    const float* __restrict__ cb, float* __restrict__ u)
{
    int idx = blockIdx.x * blockDim.x + threadIdx.x;   // element-group id
    if (idx >= MROWS * ISZ / 4) return;
    int i4 = (idx & (ISZ / 4 - 1)) * 4;   // first channel of the group
    int row = idx >> 7;                   // ISZ/4 = 128
    int l = row & (LSEQ - 1);

    // conv weights for 4 channels: cw is [I][4]
    float4 wr0 = ((const float4*)cw)[i4 + 0];
    float4 wr1 = ((const float4*)cw)[i4 + 1];
    float4 wr2 = ((const float4*)cw)[i4 + 2];
    float4 wr3 = ((const float4*)cw)[i4 + 3];
    float4 bias = *(const float4*)(cb + i4);

    const float* p = proj + (size_t)row * (2 * ISZ) + i4;
    float4 x0 = *(const float4*)p;                                  // t = l
    float4 acc = make_float4(bias.x + wr0.w * x0.x, bias.y + wr1.w * x0.y,
                             bias.z + wr2.w * x0.z, bias.w + wr3.w * x0.w);
    if (l >= 1) {
        float4 x1 = *(const float4*)(p - 2 * ISZ);
        acc.x += wr0.z * x1.x; acc.y += wr1.z * x1.y;
        acc.z += wr2.z * x1.z; acc.w += wr3.z * x1.w;
    }
    if (l >= 2) {
        float4 x2 = *(const float4*)(p - 4 * ISZ);
        acc.x += wr0.y * x2.x; acc.y += wr1.y * x2.y;
        acc.z += wr2.y * x2.z; acc.w += wr3.y * x2.w;
    }
    if (l >= 3) {
        float4 x3 = *(const float4*)(p - 6 * ISZ);
        acc.x += wr0.x * x3.x; acc.y += wr1.x * x3.y;
        acc.z += wr2.x * x3.z; acc.w += wr3.x * x3.w;
    }
    float4 o;
    o.x = acc.x / (1.0f + __expf(-acc.x));
    o.y = acc.y / (1.0f + __expf(-acc.y));
    o.z = acc.z / (1.0f + __expf(-acc.z));
    o.w = acc.w / (1.0f + __expf(-acc.w));
    *(float4*)(u + (size_t)row * ISZ + i4) = o;
}

// -------------------- selective scan --------------------
// Block: 256 threads = 64 channels x 4 lanes (each lane owns 4 of the 16 state dims).
// Grid: (I/64, B). Sequential over L in 32-step shared-memory chunks.
__global__ void __launch_bounds__(256) scan_kernel(
    const float* __restrict__ dt, const float* __restrict__ u,
    const float* __restrict__ ssm, const float* __restrict__ proj,
    const float* __restrict__ A_log, const float* __restrict__ Dp,
    float* __restrict__ y)
{
    constexpr int CH = 64, TS = 32;
    __shared__ float sdt[TS][CH], su[TS][CH], sgate[TS][CH], sy[TS][CH];
    __shared__ float sB[TS][SSZ], sC[TS][SSZ];

    int b = blockIdx.y;
    int i0 = blockIdx.x * CH;
    int tid = threadIdx.x;
    int sg4 = tid & 3;
    int c = tid >> 2;
    int i = i0 + c;

    float Acoef[4];
#pragma unroll
    for (int j = 0; j < 4; j++) Acoef[j] = -__expf(A_log[i * SSZ + sg4 * 4 + j]);
    float Dv = Dp[i];
    float st[4] = {0.f, 0.f, 0.f, 0.f};

    for (int t0 = 0; t0 < LSEQ; t0 += TS) {
        for (int e = tid; e < TS * CH; e += 256) {
            int t = e / CH, cc = e % CH;
            size_t r = (size_t)b * LSEQ + t0 + t;
            sdt[t][cc]   = dt[r * ISZ + i0 + cc];
            su[t][cc]    = u[r * ISZ + i0 + cc];
            sgate[t][cc] = proj[r * (2 * ISZ) + ISZ + i0 + cc];
        }
        for (int e = tid; e < TS * SSZ; e += 256) {
            int t = e / SSZ, s = e % SSZ;
            size_t r = (size_t)b * LSEQ + t0 + t;
            sB[t][s] = ssm[r * NSSM + RSZ + s];
            sC[t][s] = ssm[r * NSSM + RSZ + SSZ + s];
        }
        __syncthreads();

#pragma unroll 4
        for (int t = 0; t < TS; t++) {
            float dtv = sdt[t][c];
            float uv = su[t][c];
            float du = dtv * uv;
            float yp = 0.0f;
#pragma unroll
            for (int j = 0; j < 4; j++) {
                int s = sg4 * 4 + j;
                float dA = __expf(dtv * Acoef[j]);
                st[j] = dA * st[j] + du * sB[t][s];
                yp += st[j] * sC[t][s];
            }
            yp += __shfl_xor_sync(0xffffffffu, yp, 1);
            yp += __shfl_xor_sync(0xffffffffu, yp, 2);
            if (sg4 == 0) {
                float g = sgate[t][c];
                sy[t][c] = (yp + uv * Dv) * (g / (1.0f + __expf(-g)));
            }
        }
        __syncthreads();

        for (int e = tid; e < TS * CH; e += 256) {
            int t = e / CH, cc = e % CH;
            y[((size_t)b * LSEQ + t0 + t) * ISZ + i0 + cc] = sy[t][cc];
        }
        __syncthreads();
    }
}

// -------------------- host launcher --------------------
extern "C" void kernel_launch(void* const* d_in, const int* in_sizes, int n_in,
                              void* d_out, int out_size)
{
    (void)in_sizes; (void)n_in; (void)out_size;
    const float* x      = (const float*)d_in[0];
    const float* norm_w = (const float*)d_in[1];
    const float* in_w   = (const float*)d_in[2];
    const float* conv_w = (const float*)d_in[3];
    const float* conv_b = (const float*)d_in[4];
    const float* xp_w   = (const float*)d_in[5];
    const float* dt_w   = (const float*)d_in[6];
    const float* dt_b   = (const float*)d_in[7];
    const float* A_log  = (const float*)d_in[8];
    const float* Dp     = (const float*)d_in[9];
    const float* out_w  = (const float*)d_in[10];
    float* out = (float*)d_out;

    float* base = nullptr;
    cudaGetSymbolAddress((void**)&base, g_scratch);
    float* h_buf  = base + OFF_H;
    float* proj   = base + OFF_PROJ;
    float* u_buf  = base + OFF_U;
    float* ssm    = base + OFF_SSM;
    float* dt_buf = base + OFF_DT;
    float* y_buf  = base + OFF_Y;

    // residual stream lives in d_out; updated in place each layer
    cudaMemcpyAsync(out, x, sizeof(float) * (size_t)MROWS * Hh,
                    cudaMemcpyDeviceToDevice, 0);

    for (int li = 0; li < NLAY; li++) {
        const float* nw  = norm_w + (size_t)li * Hh;
        const float* iw  = in_w   + (size_t)li * 2 * ISZ * Hh;
        const float* cw  = conv_w + (size_t)li * ISZ * KC;
        const float* cb  = conv_b + (size_t)li * ISZ;
        const float* xpw = xp_w   + (size_t)li * NSSM * ISZ;
        const float* dtw = dt_w   + (size_t)li * ISZ * RSZ;
        const float* dtb = dt_b   + (size_t)li * ISZ;
        const float* al  = A_log  + (size_t)li * ISZ * SSZ;
        const float* dd  = Dp     + (size_t)li * ISZ;
        const float* ow  = out_w  + (size_t)li * Hh * ISZ;

        // 1) RMSNorm
        rmsnorm_kernel<<<MROWS / 8, 256>>>(out, nw, h_buf);

        // 2) in_proj (fp16 TC): proj[32768,1024] = h[32768,256] @ iw[1024,256]^T
        hgemm_kernel<EPI_NONE>
            <<<dim3(2 * ISZ / 128, MROWS / 128), 256>>>(
                h_buf, iw, proj, Hh, Hh, Hh, 2 * ISZ);

        // 3) depthwise causal conv + SiLU -> u
        conv_silu_kernel<<<(MROWS * ISZ / 4) / 256, 256>>>(proj, cw, cb, u_buf);

        // 4) x_proj (fp32, precision-critical): ssm[32768,48] = u @ xpw^T
        //    TM=8 x TN=6 -> 48 FFMA : 14 LDS per k
        gemm_kernel<128, 48, 16, 8, 6, EPI_NONE>
            <<<dim3(1, MROWS / 128), 128>>>(
                u_buf, xpw, ssm, ISZ, ISZ, ISZ, NSSM, nullptr);

        // 5) dt_proj + softplus (fp32)
        gemm128_kernel<EPI_SOFTPLUS_BIAS>
            <<<dim3(ISZ / 128, MROWS / 128), 256>>>(
                ssm, dtw, dt_buf, RSZ, NSSM, RSZ, ISZ, dtb);

        // 6) selective scan (+ D-skip + gate) -> y
        scan_kernel<<<dim3(ISZ / 64, BATCH), 256>>>(
            dt_buf, u_buf, ssm, proj, al, dd, y_buf);

        // 7) out_proj + residual (fp16 TC): out += y @ ow[256,512]^T
        hgemm_kernel<EPI_RESADD>
            <<<dim3(Hh / 128, MROWS / 128), 256>>>(
                y_buf, ow, out, ISZ, ISZ, ISZ, Hh);
    }
}

// round 13
// speedup vs baseline: 1.0816x; 1.0816x over previous
#include <cuda_runtime.h>
#include <cuda_fp16.h>
#include <math.h>
#include <stdint.h>

// Problem constants (fixed by the reference)
#define Hh    256
#define ISZ   512
#define SSZ   16
#define RSZ   16
#define KC    4
#define NLAY  8
#define BATCH 16
#define LSEQ  2048
#define MROWS (BATCH * LSEQ)      // 32768
#define NSSM  (RSZ + 2 * SSZ)     // 48

// -------------------- static scratch (no allocations allowed) --------------------
__device__ __align__(256) float g_scratch[(size_t)MROWS * 2864];

#define OFF_H    ((size_t)0)
#define OFF_PROJ ((size_t)MROWS * Hh)
#define OFF_U    (OFF_PROJ + (size_t)MROWS * 2 * ISZ)
#define OFF_SSM  (OFF_U + (size_t)MROWS * ISZ)
#define OFF_DT   (OFF_SSM + (size_t)MROWS * NSSM)
#define OFF_Y    (OFF_DT + (size_t)MROWS * ISZ)

// -------------------- RMSNorm: one warp per row of 256 --------------------
__global__ void __launch_bounds__(256) rmsnorm_kernel(
    const float* __restrict__ x, const float* __restrict__ w,
    float* __restrict__ out)
{
    int warp = (blockIdx.x * blockDim.x + threadIdx.x) >> 5;
    int lane = threadIdx.x & 31;
    if (warp >= MROWS) return;
    const float4* xr = (const float4*)(x + (size_t)warp * Hh);
    float4 v0 = xr[lane * 2 + 0];
    float4 v1 = xr[lane * 2 + 1];
    float ss = v0.x * v0.x + v0.y * v0.y + v0.z * v0.z + v0.w * v0.w
             + v1.x * v1.x + v1.y * v1.y + v1.z * v1.z + v1.w * v1.w;
#pragma unroll
    for (int o = 16; o > 0; o >>= 1) ss += __shfl_xor_sync(0xffffffffu, ss, o);
    float sc = rsqrtf(ss * (1.0f / Hh) + 1e-5f);
    const float4* wr = (const float4*)w;
    float4 w0 = wr[lane * 2 + 0];
    float4 w1 = wr[lane * 2 + 1];
    float4 o0 = make_float4(v0.x * sc * w0.x, v0.y * sc * w0.y,
                            v0.z * sc * w0.z, v0.w * sc * w0.w);
    float4 o1 = make_float4(v1.x * sc * w1.x, v1.y * sc * w1.y,
                            v1.z * sc * w1.z, v1.w * sc * w1.w);
    float4* orow = (float4*)(out + (size_t)warp * Hh);
    orow[lane * 2 + 0] = o0;
    orow[lane * 2 + 1] = o1;
}

enum { EPI_NONE = 0, EPI_SOFTPLUS_BIAS = 1, EPI_RESADD = 2 };

// -------------------- fp16 tensor-core GEMM (mma.sync m16n8k16) --------------------
// C[m,n] = sum_k A[m,k] * B[n,k]; A,B fp32 in gmem, converted to fp16 while
// staging into smem. BM=BN=128, BK=32, 256 threads = 4(M) x 2(N) warps,
// warp tile 32x64 = 2 x 8 m16n8k16 fragments, fp32 accumulate.
// Smem: k-major rows of 16 f16x2 words, XOR swizzle (kw ^ 2*(row&7)).

__device__ __forceinline__ uint32_t f2h2(float a, float b) {
    __half2 h = __floats2half2_rn(a, b);
    return *reinterpret_cast<uint32_t*>(&h);
}

__device__ __forceinline__ void mma16816(float* c, const uint32_t* a,
                                         const uint32_t* b) {
    asm volatile(
        "mma.sync.aligned.m16n8k16.row.col.f32.f16.f16.f32 "
        "{%0,%1,%2,%3}, {%4,%5,%6,%7}, {%8,%9}, {%0,%1,%2,%3};\n"
        : "+f"(c[0]), "+f"(c[1]), "+f"(c[2]), "+f"(c[3])
        : "r"(a[0]), "r"(a[1]), "r"(a[2]), "r"(a[3]), "r"(b[0]), "r"(b[1]));
}

template <int EPI>
__global__ void __launch_bounds__(256) hgemm_kernel(
    const float* __restrict__ A, const float* __restrict__ B,
    float* __restrict__ C, int K, int lda, int ldb, int ldc)
{
    __shared__ uint32_t As[2][128][16];
    __shared__ uint32_t Bs[2][128][16];

    int tid = threadIdx.x;
    int m0 = blockIdx.y * 128, n0 = blockIdx.x * 128;
    int warp = tid >> 5, lane = tid & 31;
    int wm = warp & 3, wn = warp >> 2;       // 4 x 2 warp grid
    int grp = lane >> 2, tig = lane & 3;

    int lrow = tid >> 1;
    int lhalf = tid & 1;
    const float* Ap = A + (size_t)(m0 + lrow) * lda + lhalf * 16;
    const float* Bp = B + (size_t)(n0 + lrow) * ldb + lhalf * 16;
    int ssw = 2 * (lrow & 7);

    float4 ra[4], rb[4];
    float acc[2][8][4];
#pragma unroll
    for (int i = 0; i < 2; i++)
#pragma unroll
        for (int j = 0; j < 8; j++)
#pragma unroll
            for (int q = 0; q < 4; q++) acc[i][j][q] = 0.0f;

#pragma unroll
    for (int i = 0; i < 4; i++) {
        ra[i] = *(const float4*)(Ap + i * 4);
        rb[i] = *(const float4*)(Bp + i * 4);
    }

    int KT = K / 32;
    int buf = 0;
#pragma unroll
    for (int i = 0; i < 4; i++) {
        int kw = lhalf * 8 + i * 2;
        As[0][lrow][kw ^ ssw] = f2h2(ra[i].x, ra[i].y);
        As[0][lrow][(kw + 1) ^ ssw] = f2h2(ra[i].z, ra[i].w);
        Bs[0][lrow][kw ^ ssw] = f2h2(rb[i].x, rb[i].y);
        Bs[0][lrow][(kw + 1) ^ ssw] = f2h2(rb[i].z, rb[i].w);
    }
    __syncthreads();

    for (int kt = 0; kt < KT; kt++) {
        if (kt + 1 < KT) {
#pragma unroll
            for (int i = 0; i < 4; i++) {
                ra[i] = *(const float4*)(Ap + (kt + 1) * 32 + i * 4);
                rb[i] = *(const float4*)(Bp + (kt + 1) * 32 + i * 4);
            }
        }
#pragma unroll
        for (int ks = 0; ks < 2; ks++) {
            int kw0 = ks * 8;
            uint32_t af[2][4];
#pragma unroll
            for (int i = 0; i < 2; i++) {
                int r = wm * 32 + i * 16 + grp;
                int sw = 2 * (r & 7);
                af[i][0] = As[buf][r][(kw0 + tig) ^ sw];
                af[i][1] = As[buf][r + 8][(kw0 + tig) ^ sw];
                af[i][2] = As[buf][r][(kw0 + tig + 4) ^ sw];
                af[i][3] = As[buf][r + 8][(kw0 + tig + 4) ^ sw];
            }
            uint32_t bf[8][2];
#pragma unroll
            for (int j = 0; j < 8; j++) {
                int c = wn * 64 + j * 8 + grp;
                int sw = 2 * (c & 7);
                bf[j][0] = Bs[buf][c][(kw0 + tig) ^ sw];
                bf[j][1] = Bs[buf][c][(kw0 + tig + 4) ^ sw];
            }
#pragma unroll
            for (int i = 0; i < 2; i++)
#pragma unroll
                for (int j = 0; j < 8; j++) mma16816(acc[i][j], af[i], bf[j]);
        }
        if (kt + 1 < KT) {
            int nb = buf ^ 1;
#pragma unroll
            for (int i = 0; i < 4; i++) {
                int kw = lhalf * 8 + i * 2;
                As[nb][lrow][kw ^ ssw] = f2h2(ra[i].x, ra[i].y);
                As[nb][lrow][(kw + 1) ^ ssw] = f2h2(ra[i].z, ra[i].w);
                Bs[nb][lrow][kw ^ ssw] = f2h2(rb[i].x, rb[i].y);
                Bs[nb][lrow][(kw + 1) ^ ssw] = f2h2(rb[i].z, rb[i].w);
            }
            __syncthreads();
            buf = nb;
        }
    }

#pragma unroll
    for (int i = 0; i < 2; i++) {
        int m = m0 + wm * 32 + i * 16 + grp;
#pragma unroll
        for (int j = 0; j < 8; j++) {
            int n = n0 + wn * 64 + j * 8 + tig * 2;
            float2* p0 = (float2*)(C + (size_t)m * ldc + n);
            float2* p1 = (float2*)(C + (size_t)(m + 8) * ldc + n);
            if (EPI == EPI_RESADD) {
                float2 v0 = *p0, v1 = *p1;
                v0.x += acc[i][j][0]; v0.y += acc[i][j][1];
                v1.x += acc[i][j][2]; v1.y += acc[i][j][3];
                *p0 = v0; *p1 = v1;
            } else {
                *p0 = make_float2(acc[i][j][0], acc[i][j][1]);
                *p1 = make_float2(acc[i][j][2], acc[i][j][3]);
            }
        }
    }
}

// -------------------- fp16 TC GEMM, BN=48 (x_proj) --------------------
// C[m,n] = sum_k A[m,k]*B[n,k], N=48. BM=128, BK=32, 256 threads,
// 4(M) x 2(N) warps, warp tile 32x24 = 2 x 3 m16n8k16 fragments.
// B staged by threads 0..95 (48 rows). Column bases {0,8,16,24,32,40} are
// multiples of 8 -> same conflict-free swizzle as hgemm_kernel.
__global__ void __launch_bounds__(256) hgemm48_kernel(
    const float* __restrict__ A, const float* __restrict__ B,
    float* __restrict__ C, int K, int lda, int ldb, int ldc)
{
    __shared__ uint32_t As[2][128][16];
    __shared__ uint32_t Bs[2][48][16];

    int tid = threadIdx.x;
    int m0 = blockIdx.y * 128;
    int warp = tid >> 5, lane = tid & 31;
    int wm = warp & 3, wn = warp >> 2;
    int grp = lane >> 2, tig = lane & 3;

    int lrow = tid >> 1;
    int lhalf = tid & 1;
    const float* Ap = A + (size_t)(m0 + lrow) * lda + lhalf * 16;
    int ssw = 2 * (lrow & 7);
    // B staging lane (threads 0..95): 48 rows x 2 halves
    bool bAct = tid < 96;
    int brow = tid >> 1;           // 0..47 when active
    const float* Bp = B + (size_t)brow * ldb + lhalf * 16;
    int bsw = 2 * (brow & 7);

    float4 ra[4], rb[4];
    float acc[2][3][4];
#pragma unroll
    for (int i = 0; i < 2; i++)
#pragma unroll
        for (int j = 0; j < 3; j++)
#pragma unroll
            for (int q = 0; q < 4; q++) acc[i][j][q] = 0.0f;

#pragma unroll
    for (int i = 0; i < 4; i++) ra[i] = *(const float4*)(Ap + i * 4);
    if (bAct)
#pragma unroll
        for (int i = 0; i < 4; i++) rb[i] = *(const float4*)(Bp + i * 4);

    int KT = K / 32;
    int buf = 0;
#pragma unroll
    for (int i = 0; i < 4; i++) {
        int kw = lhalf * 8 + i * 2;
        As[0][lrow][kw ^ ssw] = f2h2(ra[i].x, ra[i].y);
        As[0][lrow][(kw + 1) ^ ssw] = f2h2(ra[i].z, ra[i].w);
    }
    if (bAct) {
#pragma unroll
        for (int i = 0; i < 4; i++) {
            int kw = lhalf * 8 + i * 2;
            Bs[0][brow][kw ^ bsw] = f2h2(rb[i].x, rb[i].y);
            Bs[0][brow][(kw + 1) ^ bsw] = f2h2(rb[i].z, rb[i].w);
        }
    }
    __syncthreads();

    for (int kt = 0; kt < KT; kt++) {
        if (kt + 1 < KT) {
#pragma unroll
            for (int i = 0; i < 4; i++)
                ra[i] = *(const float4*)(Ap + (kt + 1) * 32 + i * 4);
            if (bAct)
#pragma unroll
                for (int i = 0; i < 4; i++)
                    rb[i] = *(const float4*)(Bp + (kt + 1) * 32 + i * 4);
        }
#pragma unroll
        for (int ks = 0; ks < 2; ks++) {
            int kw0 = ks * 8;
            uint32_t af[2][4];
#pragma unroll
            for (int i = 0; i < 2; i++) {
                int r = wm * 32 + i * 16 + grp;
                int sw = 2 * (r & 7);
                af[i][0] = As[buf][r][(kw0 + tig) ^ sw];
                af[i][1] = As[buf][r + 8][(kw0 + tig) ^ sw];
                af[i][2] = As[buf][r][(kw0 + tig + 4) ^ sw];
                af[i][3] = As[buf][r + 8][(kw0 + tig + 4) ^ sw];
            }
            uint32_t bf[3][2];
#pragma unroll
            for (int j = 0; j < 3; j++) {
                int c = wn * 24 + j * 8 + grp;
                int sw = 2 * (c & 7);
                bf[j][0] = Bs[buf][c][(kw0 + tig) ^ sw];
                bf[j][1] = Bs[buf][c][(kw0 + tig + 4) ^ sw];
            }
#pragma unroll
            for (int i = 0; i < 2; i++)
#pragma unroll
                for (int j = 0; j < 3; j++) mma16816(acc[i][j], af[i], bf[j]);
        }
        if (kt + 1 < KT) {
            int nb = buf ^ 1;
#pragma unroll
            for (int i = 0; i < 4; i++) {
                int kw = lhalf * 8 + i * 2;
                As[nb][lrow][kw ^ ssw] = f2h2(ra[i].x, ra[i].y);
                As[nb][lrow][(kw + 1) ^ ssw] = f2h2(ra[i].z, ra[i].w);
            }
            if (bAct) {
#pragma unroll
                for (int i = 0; i < 4; i++) {
                    int kw = lhalf * 8 + i * 2;
                    Bs[nb][brow][kw ^ bsw] = f2h2(rb[i].x, rb[i].y);
                    Bs[nb][brow][(kw + 1) ^ bsw] = f2h2(rb[i].z, rb[i].w);
                }
            }
            __syncthreads();
            buf = nb;
        }
    }

#pragma unroll
    for (int i = 0; i < 2; i++) {
        int m = m0 + wm * 32 + i * 16 + grp;
#pragma unroll
        for (int j = 0; j < 3; j++) {
            int n = wn * 24 + j * 8 + tig * 2;
            *(float2*)(C + (size_t)m * ldc + n) =
                make_float2(acc[i][j][0], acc[i][j][1]);
            *(float2*)(C + (size_t)(m + 8) * ldc + n) =
                make_float2(acc[i][j][2], acc[i][j][3]);
        }
    }
}

// -------------------- 128x128x8 fp32 SGEMM (dt_proj) --------------------
template <int EPI>
__global__ void __launch_bounds__(256) gemm128_kernel(
    const float* __restrict__ A, const float* __restrict__ B,
    float* __restrict__ C, int K, int lda, int ldb, int ldc,
    const float* __restrict__ bias)
{
    __shared__ float As[2][8][132];
    __shared__ float Bs[2][8][132];

    int tid = threadIdx.x;
    int m0 = blockIdx.y * 128;
    int n0 = blockIdx.x * 128;

    int lm = tid >> 1;
    int lk = (tid & 1) * 4;
    const float* Aptr = A + (size_t)(m0 + lm) * lda + lk;
    const float* Bptr = B + (size_t)(n0 + lm) * ldb + lk;

    int tx = tid & 15;
    int ty = tid >> 4;

    float acc[8][8];
#pragma unroll
    for (int i = 0; i < 8; i++)
#pragma unroll
        for (int j = 0; j < 8; j++) acc[i][j] = 0.0f;

    float4 ra = *(const float4*)Aptr;
    float4 rb = *(const float4*)Bptr;

    int KT = K / 8;
    int buf = 0;
    for (int kt = 0; kt < KT; kt++) {
        As[buf][lk + 0][lm] = ra.x;
        As[buf][lk + 1][lm] = ra.y;
        As[buf][lk + 2][lm] = ra.z;
        As[buf][lk + 3][lm] = ra.w;
        Bs[buf][lk + 0][lm] = rb.x;
        Bs[buf][lk + 1][lm] = rb.y;
        Bs[buf][lk + 2][lm] = rb.z;
        Bs[buf][lk + 3][lm] = rb.w;
        __syncthreads();
        if (kt + 1 < KT) {
            ra = *(const float4*)(Aptr + (kt + 1) * 8);
            rb = *(const float4*)(Bptr + (kt + 1) * 8);
        }
#pragma unroll
        for (int k = 0; k < 8; k++) {
            float4 a0 = *(const float4*)&As[buf][k][ty * 8];
            float4 a1 = *(const float4*)&As[buf][k][ty * 8 + 4];
            float4 b0 = *(const float4*)&Bs[buf][k][tx * 8];
            float4 b1 = *(const float4*)&Bs[buf][k][tx * 8 + 4];
            float av[8] = {a0.x, a0.y, a0.z, a0.w, a1.x, a1.y, a1.z, a1.w};
            float bv[8] = {b0.x, b0.y, b0.z, b0.w, b1.x, b1.y, b1.z, b1.w};
#pragma unroll
            for (int i = 0; i < 8; i++)
#pragma unroll
                for (int j = 0; j < 8; j++) acc[i][j] += av[i] * bv[j];
        }
        buf ^= 1;
    }

#pragma unroll
    for (int i = 0; i < 8; i++) {
        int m = m0 + ty * 8 + i;
        float* crow = C + (size_t)m * ldc + n0 + tx * 8;
        if (EPI == EPI_NONE) {
            ((float4*)crow)[0] = make_float4(acc[i][0], acc[i][1], acc[i][2], acc[i][3]);
            ((float4*)crow)[1] = make_float4(acc[i][4], acc[i][5], acc[i][6], acc[i][7]);
        } else if (EPI == EPI_SOFTPLUS_BIAS) {
            float o[8];
#pragma unroll
            for (int j = 0; j < 8; j++) {
                float v = acc[i][j] + bias[n0 + tx * 8 + j];
                o[j] = fmaxf(v, 0.0f) + log1pf(__expf(-fabsf(v)));
            }
            ((float4*)crow)[0] = make_float4(o[0], o[1], o[2], o[3]);
            ((float4*)crow)[1] = make_float4(o[4], o[5], o[6], o[7]);
        } else {
            float4 c0 = ((float4*)crow)[0];
            float4 c1 = ((float4*)crow)[1];
            c0.x += acc[i][0]; c0.y += acc[i][1]; c0.z += acc[i][2]; c0.w += acc[i][3];
            c1.x += acc[i][4]; c1.y += acc[i][5]; c1.z += acc[i][6]; c1.w += acc[i][7];
            ((float4*)crow)[0] = c0;
            ((float4*)crow)[1] = c1;
        }
    }
}

// -------------------- depthwise causal conv + bias + SiLU, L-tiled ------------
// Each thread: 4 channels x 8 consecutive timesteps. Reads 11 rows per 8
// outputs (vs 4 per 1 before). Zero-fill of l<0 rows matches the reference's
// causal zero-padding and guards batch boundaries (l0==0 -> j<3 zeroed).
__global__ void __launch_bounds__(256) conv_silu_kernel(
    const float* __restrict__ proj, const float* __restrict__ cw,
    const float* __restrict__ cb, float* __restrict__ u)
{
    int idx = blockIdx.x * blockDim.x + threadIdx.x;
    if (idx >= (MROWS / 8) * (ISZ / 4)) return;
    int i4 = (idx & (ISZ / 4 - 1)) * 4;      // channel group
    int rb = idx >> 7;                        // row-block id
    int l0 = (rb & (LSEQ / 8 - 1)) * 8;
    size_t row0 = (size_t)rb * 8;             // = b*LSEQ + l0

    float4 wr0 = ((const float4*)cw)[i4 + 0];
    float4 wr1 = ((const float4*)cw)[i4 + 1];
    float4 wr2 = ((const float4*)cw)[i4 + 2];
    float4 wr3 = ((const float4*)cw)[i4 + 3];
    float4 bias = *(const float4*)(cb + i4);

    float4 val[11];
#pragma unroll
    for (int j = 0; j < 11; j++) {
        int l = l0 + j - 3;
        if (l >= 0)
            val[j] = *(const float4*)(proj + (row0 + j - 3) * (2 * ISZ) + i4);
        else
            val[j] = make_float4(0.f, 0.f, 0.f, 0.f);
    }

#pragma unroll
    for (int k = 0; k < 8; k++) {
        // u[l0+k] = silu(cb + w3*x[l] + w2*x[l-1] + w1*x[l-2] + w0*x[l-3])
        float4 a;
        a.x = bias.x + wr0.w * val[k + 3].x + wr0.z * val[k + 2].x
                     + wr0.y * val[k + 1].x + wr0.x * val[k].x;
        a.y = bias.y + wr1.w * val[k + 3].y + wr1.z * val[k + 2].y
                     + wr1.y * val[k + 1].y + wr1.x * val[k].y;
        a.z = bias.z + wr2.w * val[k + 3].z + wr2.z * val[k + 2].z
                     + wr2.y * val[k + 1].z + wr2.x * val[k].z;
        a.w = bias.w + wr3.w * val[k + 3].w + wr3.z * val[k + 2].w
                     + wr3.y * val[k + 1].w + wr3.x * val[k].w;
        float4 o;
        o.x = a.x / (1.0f + __expf(-a.x));
        o.y = a.y / (1.0f + __expf(-a.y));
        o.z = a.z / (1.0f + __expf(-a.z));
        o.w = a.w / (1.0f + __expf(-a.w));
        *(float4*)(u + (row0 + k) * ISZ + i4) = o;
    }
}

// -------------------- selective scan --------------------
__global__ void __launch_bounds__(256) scan_kernel(
    const float* __restrict__ dt, const float* __restrict__ u,
    const float* __restrict__ ssm, const float* __restrict__ proj,
    const float* __restrict__ A_log, const float* __restrict__ Dp,
    float* __restrict__ y)
{
    constexpr int CH = 64, TS = 32;
    __shared__ float sdt[TS][CH], su[TS][CH], sgate[TS][CH], sy[TS][CH];
    __shared__ float sB[TS][SSZ], sC[TS][SSZ];

    int b = blockIdx.y;
    int i0 = blockIdx.x * CH;
    int tid = threadIdx.x;
    int sg4 = tid & 3;
    int c = tid >> 2;
    int i = i0 + c;

    float Acoef[4];
#pragma unroll
    for (int j = 0; j < 4; j++) Acoef[j] = -__expf(A_log[i * SSZ + sg4 * 4 + j]);
    float Dv = Dp[i];
    float st[4] = {0.f, 0.f, 0.f, 0.f};

    for (int t0 = 0; t0 < LSEQ; t0 += TS) {
        for (int e = tid; e < TS * CH; e += 256) {
            int t = e / CH, cc = e % CH;
            size_t r = (size_t)b * LSEQ + t0 + t;
            sdt[t][cc]   = dt[r * ISZ + i0 + cc];
            su[t][cc]    = u[r * ISZ + i0 + cc];
            sgate[t][cc] = proj[r * (2 * ISZ) + ISZ + i0 + cc];
        }
        for (int e = tid; e < TS * SSZ; e += 256) {
            int t = e / SSZ, s = e % SSZ;
            size_t r = (size_t)b * LSEQ + t0 + t;
            sB[t][s] = ssm[r * NSSM + RSZ + s];
            sC[t][s] = ssm[r * NSSM + RSZ + SSZ + s];
        }
        __syncthreads();

#pragma unroll 4
        for (int t = 0; t < TS; t++) {
            float dtv = sdt[t][c];
            float uv = su[t][c];
            float du = dtv * uv;
            float yp = 0.0f;
#pragma unroll
            for (int j = 0; j < 4; j++) {
                int s = sg4 * 4 + j;
                float dA = __expf(dtv * Acoef[j]);
                st[j] = dA * st[j] + du * sB[t][s];
                yp += st[j] * sC[t][s];
            }
            yp += __shfl_xor_sync(0xffffffffu, yp, 1);
            yp += __shfl_xor_sync(0xffffffffu, yp, 2);
            if (sg4 == 0) {
                float g = sgate[t][c];
                sy[t][c] = (yp + uv * Dv) * (g / (1.0f + __expf(-g)));
            }
        }
        __syncthreads();

        for (int e = tid; e < TS * CH; e += 256) {
            int t = e / CH, cc = e % CH;
            y[((size_t)b * LSEQ + t0 + t) * ISZ + i0 + cc] = sy[t][cc];
        }
        __syncthreads();
    }
}

// -------------------- host launcher --------------------
extern "C" void kernel_launch(void* const* d_in, const int* in_sizes, int n_in,
                              void* d_out, int out_size)
{
    (void)in_sizes; (void)n_in; (void)out_size;
    const float* x      = (const float*)d_in[0];
    const float* norm_w = (const float*)d_in[1];
    const float* in_w   = (const float*)d_in[2];
    const float* conv_w = (const float*)d_in[3];
    const float* conv_b = (const float*)d_in[4];
    const float* xp_w   = (const float*)d_in[5];
    const float* dt_w   = (const float*)d_in[6];
    const float* dt_b   = (const float*)d_in[7];
    const float* A_log  = (const float*)d_in[8];
    const float* Dp     = (const float*)d_in[9];
    const float* out_w  = (const float*)d_in[10];
    float* out = (float*)d_out;

    float* base = nullptr;
    cudaGetSymbolAddress((void**)&base, g_scratch);
    float* h_buf  = base + OFF_H;
    float* proj   = base + OFF_PROJ;
    float* u_buf  = base + OFF_U;
    float* ssm    = base + OFF_SSM;
    float* dt_buf = base + OFF_DT;
    float* y_buf  = base + OFF_Y;

    // residual stream lives in d_out; updated in place each layer
    cudaMemcpyAsync(out, x, sizeof(float) * (size_t)MROWS * Hh,
                    cudaMemcpyDeviceToDevice, 0);

    for (int li = 0; li < NLAY; li++) {
        const float* nw  = norm_w + (size_t)li * Hh;
        const float* iw  = in_w   + (size_t)li * 2 * ISZ * Hh;
        const float* cw  = conv_w + (size_t)li * ISZ * KC;
        const float* cb  = conv_b + (size_t)li * ISZ;
        const float* xpw = xp_w   + (size_t)li * NSSM * ISZ;
        const float* dtw = dt_w   + (size_t)li * ISZ * RSZ;
        const float* dtb = dt_b   + (size_t)li * ISZ;
        const float* al  = A_log  + (size_t)li * ISZ * SSZ;
        const float* dd  = Dp     + (size_t)li * ISZ;
        const float* ow  = out_w  + (size_t)li * Hh * ISZ;

        // 1) RMSNorm
        rmsnorm_kernel<<<MROWS / 8, 256>>>(out, nw, h_buf);

        // 2) in_proj (fp16 TC)
        hgemm_kernel<EPI_NONE>
            <<<dim3(2 * ISZ / 128, MROWS / 128), 256>>>(
                h_buf, iw, proj, Hh, Hh, Hh, 2 * ISZ);

        // 3) depthwise causal conv + SiLU -> u (L-tiled)
        conv_silu_kernel<<<((MROWS / 8) * (ISZ / 4)) / 256, 256>>>(
            proj, cw, cb, u_buf);

        // 4) x_proj (fp16 TC, BN=48): ssm[32768,48] = u @ xpw^T
        hgemm48_kernel<<<dim3(1, MROWS / 128), 256>>>(
            u_buf, xpw, ssm, ISZ, ISZ, ISZ, NSSM);

        // 5) dt_proj + softplus (fp32)
        gemm128_kernel<EPI_SOFTPLUS_BIAS>
            <<<dim3(ISZ / 128, MROWS / 128), 256>>>(
                ssm, dtw, dt_buf, RSZ, NSSM, RSZ, ISZ, dtb);

        // 6) selective scan (+ D-skip + gate) -> y
        scan_kernel<<<dim3(ISZ / 64, BATCH), 256>>>(
            dt_buf, u_buf, ssm, proj, al, dd, y_buf);

        // 7) out_proj + residual (fp16 TC)
        hgemm_kernel<EPI_RESADD>
            <<<dim3(Hh / 128, MROWS / 128), 256>>>(
                y_buf, ow, out, ISZ, ISZ, ISZ, Hh);
    }
}

// round 14
// speedup vs baseline: 1.1899x; 1.1002x over previous
#include <cuda_runtime.h>
#include <cuda_fp16.h>
#include <math.h>
#include <stdint.h>

// Problem constants (fixed by the reference)
#define Hh    256
#define ISZ   512
#define SSZ   16
#define RSZ   16
#define KC    4
#define NLAY  8
#define BATCH 16
#define LSEQ  2048
#define MROWS (BATCH * LSEQ)      // 32768
#define NSSM  (RSZ + 2 * SSZ)     // 48

// -------------------- static scratch (no allocations allowed) --------------------
// Offsets are in float units; half buffers reuse the same regions (half the bytes).
__device__ __align__(256) float g_scratch[(size_t)MROWS * 2864];

#define OFF_H    ((size_t)0)
#define OFF_PROJ ((size_t)MROWS * Hh)
#define OFF_U    (OFF_PROJ + (size_t)MROWS * 2 * ISZ)
#define OFF_SSM  (OFF_U + (size_t)MROWS * ISZ)
#define OFF_DT   (OFF_SSM + (size_t)MROWS * NSSM)
#define OFF_Y    (OFF_DT + (size_t)MROWS * ISZ)

__device__ __forceinline__ uint32_t f2h2(float a, float b) {
    __half2 h = __floats2half2_rn(a, b);
    return *reinterpret_cast<uint32_t*>(&h);
}

// -------------------- RMSNorm: one warp per row of 256; fp16 output ----------
__global__ void __launch_bounds__(256) rmsnorm_kernel(
    const float* __restrict__ x, const float* __restrict__ w,
    __half* __restrict__ out)
{
    int warp = (blockIdx.x * blockDim.x + threadIdx.x) >> 5;
    int lane = threadIdx.x & 31;
    if (warp >= MROWS) return;
    const float4* xr = (const float4*)(x + (size_t)warp * Hh);
    float4 v0 = xr[lane * 2 + 0];
    float4 v1 = xr[lane * 2 + 1];
    float ss = v0.x * v0.x + v0.y * v0.y + v0.z * v0.z + v0.w * v0.w
             + v1.x * v1.x + v1.y * v1.y + v1.z * v1.z + v1.w * v1.w;
#pragma unroll
    for (int o = 16; o > 0; o >>= 1) ss += __shfl_xor_sync(0xffffffffu, ss, o);
    float sc = rsqrtf(ss * (1.0f / Hh) + 1e-5f);
    const float4* wr = (const float4*)w;
    float4 w0 = wr[lane * 2 + 0];
    float4 w1 = wr[lane * 2 + 1];
    uint4 pk;
    pk.x = f2h2(v0.x * sc * w0.x, v0.y * sc * w0.y);
    pk.y = f2h2(v0.z * sc * w0.z, v0.w * sc * w0.w);
    pk.z = f2h2(v1.x * sc * w1.x, v1.y * sc * w1.y);
    pk.w = f2h2(v1.z * sc * w1.z, v1.w * sc * w1.w);
    ((uint4*)(out + (size_t)warp * Hh))[lane] = pk;
}

enum { EPI_NONE = 0, EPI_RESADD = 2 };

// load 16 consecutive k-elements as 8 f16x2 words (w[i] = k-pair {2i, 2i+1})
template <bool H>
__device__ __forceinline__ void load_row16(const void* __restrict__ p,
                                           size_t off, uint32_t w[8]) {
    if (H) {
        const uint4* q = (const uint4*)((const __half*)p + off);
        uint4 a = q[0], b = q[1];
        w[0] = a.x; w[1] = a.y; w[2] = a.z; w[3] = a.w;
        w[4] = b.x; w[5] = b.y; w[6] = b.z; w[7] = b.w;
    } else {
        const float4* q = (const float4*)((const float*)p + off);
        float4 f0 = q[0], f1 = q[1], f2 = q[2], f3 = q[3];
        w[0] = f2h2(f0.x, f0.y); w[1] = f2h2(f0.z, f0.w);
        w[2] = f2h2(f1.x, f1.y); w[3] = f2h2(f1.z, f1.w);
        w[4] = f2h2(f2.x, f2.y); w[5] = f2h2(f2.z, f2.w);
        w[6] = f2h2(f3.x, f3.y); w[7] = f2h2(f3.z, f3.w);
    }
}

__device__ __forceinline__ void mma16816(float* c, const uint32_t* a,
                                         const uint32_t* b) {
    asm volatile(
        "mma.sync.aligned.m16n8k16.row.col.f32.f16.f16.f32 "
        "{%0,%1,%2,%3}, {%4,%5,%6,%7}, {%8,%9}, {%0,%1,%2,%3};\n"
        : "+f"(c[0]), "+f"(c[1]), "+f"(c[2]), "+f"(c[3])
        : "r"(a[0]), "r"(a[1]), "r"(a[2]), "r"(a[3]), "r"(b[0]), "r"(b[1]));
}

// -------------------- fp16 TC GEMM (BM=BN=128, BK=32) --------------------
// C[m,n] = sum_k A[m,k]*B[n,k]. AH: A stored fp16. CHALF: C written fp16.
// B always fp32 (weights; L2-resident). XOR swizzle (word ^ 2*(row&7)).
template <int EPI, bool AH, bool CHALF>
__global__ void __launch_bounds__(256) hgemm_kernel(
    const void* __restrict__ A, const float* __restrict__ B,
    void* __restrict__ C, int K, int lda, int ldb, int ldc)
{
    __shared__ uint32_t As[2][128][16];
    __shared__ uint32_t Bs[2][128][16];

    int tid = threadIdx.x;
    int m0 = blockIdx.y * 128, n0 = blockIdx.x * 128;
    int warp = tid >> 5, lane = tid & 31;
    int wm = warp & 3, wn = warp >> 2;
    int grp = lane >> 2, tig = lane & 3;

    int lrow = tid >> 1;
    int lhalf = tid & 1;
    size_t aoff = (size_t)(m0 + lrow) * lda + lhalf * 16;
    size_t boff = (size_t)(n0 + lrow) * ldb + lhalf * 16;
    int ssw = 2 * (lrow & 7);

    uint32_t wa[8], wb[8];
    float acc[2][8][4];
#pragma unroll
    for (int i = 0; i < 2; i++)
#pragma unroll
        for (int j = 0; j < 8; j++)
#pragma unroll
            for (int q = 0; q < 4; q++) acc[i][j][q] = 0.0f;

    load_row16<AH>(A, aoff, wa);
    load_row16<false>(B, boff, wb);

    int KT = K / 32;
    int buf = 0;
#pragma unroll
    for (int i = 0; i < 8; i++) {
        As[0][lrow][(lhalf * 8 + i) ^ ssw] = wa[i];
        Bs[0][lrow][(lhalf * 8 + i) ^ ssw] = wb[i];
    }
    __syncthreads();

    for (int kt = 0; kt < KT; kt++) {
        if (kt + 1 < KT) {
            load_row16<AH>(A, aoff + (size_t)(kt + 1) * 32, wa);
            load_row16<false>(B, boff + (size_t)(kt + 1) * 32, wb);
        }
#pragma unroll
        for (int ks = 0; ks < 2; ks++) {
            int kw0 = ks * 8;
            uint32_t af[2][4];
#pragma unroll
            for (int i = 0; i < 2; i++) {
                int r = wm * 32 + i * 16 + grp;
                int sw = 2 * (r & 7);
                af[i][0] = As[buf][r][(kw0 + tig) ^ sw];
                af[i][1] = As[buf][r + 8][(kw0 + tig) ^ sw];
                af[i][2] = As[buf][r][(kw0 + tig + 4) ^ sw];
                af[i][3] = As[buf][r + 8][(kw0 + tig + 4) ^ sw];
            }
            uint32_t bf[8][2];
#pragma unroll
            for (int j = 0; j < 8; j++) {
                int c = wn * 64 + j * 8 + grp;
                int sw = 2 * (c & 7);
                bf[j][0] = Bs[buf][c][(kw0 + tig) ^ sw];
                bf[j][1] = Bs[buf][c][(kw0 + tig + 4) ^ sw];
            }
#pragma unroll
            for (int i = 0; i < 2; i++)
#pragma unroll
                for (int j = 0; j < 8; j++) mma16816(acc[i][j], af[i], bf[j]);
        }
        if (kt + 1 < KT) {
            int nb = buf ^ 1;
#pragma unroll
            for (int i = 0; i < 8; i++) {
                As[nb][lrow][(lhalf * 8 + i) ^ ssw] = wa[i];
                Bs[nb][lrow][(lhalf * 8 + i) ^ ssw] = wb[i];
            }
            __syncthreads();
            buf = nb;
        }
    }

#pragma unroll
    for (int i = 0; i < 2; i++) {
        int m = m0 + wm * 32 + i * 16 + grp;
#pragma unroll
        for (int j = 0; j < 8; j++) {
            int n = n0 + wn * 64 + j * 8 + tig * 2;
            if (CHALF) {
                __half* Ch = (__half*)C;
                *(__half2*)(Ch + (size_t)m * ldc + n) =
                    __floats2half2_rn(acc[i][j][0], acc[i][j][1]);
                *(__half2*)(Ch + (size_t)(m + 8) * ldc + n) =
                    __floats2half2_rn(acc[i][j][2], acc[i][j][3]);
            } else {
                float* Cf = (float*)C;
                float2* p0 = (float2*)(Cf + (size_t)m * ldc + n);
                float2* p1 = (float2*)(Cf + (size_t)(m + 8) * ldc + n);
                if (EPI == EPI_RESADD) {
                    float2 v0 = *p0, v1 = *p1;
                    v0.x += acc[i][j][0]; v0.y += acc[i][j][1];
                    v1.x += acc[i][j][2]; v1.y += acc[i][j][3];
                    *p0 = v0; *p1 = v1;
                } else {
                    *p0 = make_float2(acc[i][j][0], acc[i][j][1]);
                    *p1 = make_float2(acc[i][j][2], acc[i][j][3]);
                }
            }
        }
    }
}

// -------------------- fp16 TC GEMM, BN=48 (x_proj); A fp16, C fp32 ------------
__global__ void __launch_bounds__(256) hgemm48_kernel(
    const __half* __restrict__ A, const float* __restrict__ B,
    float* __restrict__ C, int K, int lda, int ldb, int ldc)
{
    __shared__ uint32_t As[2][128][16];
    __shared__ uint32_t Bs[2][48][16];

    int tid = threadIdx.x;
    int m0 = blockIdx.y * 128;
    int warp = tid >> 5, lane = tid & 31;
    int wm = warp & 3, wn = warp >> 2;
    int grp = lane >> 2, tig = lane & 3;

    int lrow = tid >> 1;
    int lhalf = tid & 1;
    size_t aoff = (size_t)(m0 + lrow) * lda + lhalf * 16;
    int ssw = 2 * (lrow & 7);
    bool bAct = tid < 96;
    int brow = tid >> 1;
    size_t boff = (size_t)brow * ldb + lhalf * 16;
    int bsw = 2 * (brow & 7);

    uint32_t wa[8], wb[8];
    float acc[2][3][4];
#pragma unroll
    for (int i = 0; i < 2; i++)
#pragma unroll
        for (int j = 0; j < 3; j++)
#pragma unroll
            for (int q = 0; q < 4; q++) acc[i][j][q] = 0.0f;

    load_row16<true>(A, aoff, wa);
    if (bAct) load_row16<false>(B, boff, wb);

    int KT = K / 32;
    int buf = 0;
#pragma unroll
    for (int i = 0; i < 8; i++)
        As[0][lrow][(lhalf * 8 + i) ^ ssw] = wa[i];
    if (bAct)
#pragma unroll
        for (int i = 0; i < 8; i++)
            Bs[0][brow][(lhalf * 8 + i) ^ bsw] = wb[i];
    __syncthreads();

    for (int kt = 0; kt < KT; kt++) {
        if (kt + 1 < KT) {
            load_row16<true>(A, aoff + (size_t)(kt + 1) * 32, wa);
            if (bAct) load_row16<false>(B, boff + (size_t)(kt + 1) * 32, wb);
        }
#pragma unroll
        for (int ks = 0; ks < 2; ks++) {
            int kw0 = ks * 8;
            uint32_t af[2][4];
#pragma unroll
            for (int i = 0; i < 2; i++) {
                int r = wm * 32 + i * 16 + grp;
                int sw = 2 * (r & 7);
                af[i][0] = As[buf][r][(kw0 + tig) ^ sw];
                af[i][1] = As[buf][r + 8][(kw0 + tig) ^ sw];
                af[i][2] = As[buf][r][(kw0 + tig + 4) ^ sw];
                af[i][3] = As[buf][r + 8][(kw0 + tig + 4) ^ sw];
            }
            uint32_t bf[3][2];
#pragma unroll
            for (int j = 0; j < 3; j++) {
                int c = wn * 24 + j * 8 + grp;
                int sw = 2 * (c & 7);
                bf[j][0] = Bs[buf][c][(kw0 + tig) ^ sw];
                bf[j][1] = Bs[buf][c][(kw0 + tig + 4) ^ sw];
            }
#pragma unroll
            for (int i = 0; i < 2; i++)
#pragma unroll
                for (int j = 0; j < 3; j++) mma16816(acc[i][j], af[i], bf[j]);
        }
        if (kt + 1 < KT) {
            int nb = buf ^ 1;
#pragma unroll
            for (int i = 0; i < 8; i++)
                As[nb][lrow][(lhalf * 8 + i) ^ ssw] = wa[i];
            if (bAct)
#pragma unroll
                for (int i = 0; i < 8; i++)
                    Bs[nb][brow][(lhalf * 8 + i) ^ bsw] = wb[i];
            __syncthreads();
            buf = nb;
        }
    }

#pragma unroll
    for (int i = 0; i < 2; i++) {
        int m = m0 + wm * 32 + i * 16 + grp;
#pragma unroll
        for (int j = 0; j < 3; j++) {
            int n = wn * 24 + j * 8 + tig * 2;
            *(float2*)(C + (size_t)m * ldc + n) =
                make_float2(acc[i][j][0], acc[i][j][1]);
            *(float2*)(C + (size_t)(m + 8) * ldc + n) =
                make_float2(acc[i][j][2], acc[i][j][3]);
        }
    }
}

// -------------------- dt_proj fp32 SGEMM (K=16) + softplus -> fp16 ------------
__global__ void __launch_bounds__(256) gemm128_dt_kernel(
    const float* __restrict__ A, const float* __restrict__ B,
    __half* __restrict__ C, int K, int lda, int ldb, int ldc,
    const float* __restrict__ bias)
{
    __shared__ float As[2][8][132];
    __shared__ float Bs[2][8][132];

    int tid = threadIdx.x;
    int m0 = blockIdx.y * 128;
    int n0 = blockIdx.x * 128;

    int lm = tid >> 1;
    int lk = (tid & 1) * 4;
    const float* Aptr = A + (size_t)(m0 + lm) * lda + lk;
    const float* Bptr = B + (size_t)(n0 + lm) * ldb + lk;

    int tx = tid & 15;
    int ty = tid >> 4;

    float acc[8][8];
#pragma unroll
    for (int i = 0; i < 8; i++)
#pragma unroll
        for (int j = 0; j < 8; j++) acc[i][j] = 0.0f;

    float4 ra = *(const float4*)Aptr;
    float4 rb = *(const float4*)Bptr;

    int KT = K / 8;
    int buf = 0;
    for (int kt = 0; kt < KT; kt++) {
        As[buf][lk + 0][lm] = ra.x;
        As[buf][lk + 1][lm] = ra.y;
        As[buf][lk + 2][lm] = ra.z;
        As[buf][lk + 3][lm] = ra.w;
        Bs[buf][lk + 0][lm] = rb.x;
        Bs[buf][lk + 1][lm] = rb.y;
        Bs[buf][lk + 2][lm] = rb.z;
        Bs[buf][lk + 3][lm] = rb.w;
        __syncthreads();
        if (kt + 1 < KT) {
            ra = *(const float4*)(Aptr + (kt + 1) * 8);
            rb = *(const float4*)(Bptr + (kt + 1) * 8);
        }
#pragma unroll
        for (int k = 0; k < 8; k++) {
            float4 a0 = *(const float4*)&As[buf][k][ty * 8];
            float4 a1 = *(const float4*)&As[buf][k][ty * 8 + 4];
            float4 b0 = *(const float4*)&Bs[buf][k][tx * 8];
            float4 b1 = *(const float4*)&Bs[buf][k][tx * 8 + 4];
            float av[8] = {a0.x, a0.y, a0.z, a0.w, a1.x, a1.y, a1.z, a1.w};
            float bv[8] = {b0.x, b0.y, b0.z, b0.w, b1.x, b1.y, b1.z, b1.w};
#pragma unroll
            for (int i = 0; i < 8; i++)
#pragma unroll
                for (int j = 0; j < 8; j++) acc[i][j] += av[i] * bv[j];
        }
        buf ^= 1;
    }

#pragma unroll
    for (int i = 0; i < 8; i++) {
        int m = m0 + ty * 8 + i;
        __half* crow = C + (size_t)m * ldc + n0 + tx * 8;
        float o[8];
#pragma unroll
        for (int j = 0; j < 8; j++) {
            float v = acc[i][j] + bias[n0 + tx * 8 + j];
            o[j] = fmaxf(v, 0.0f) + log1pf(__expf(-fabsf(v)));
        }
        uint4 pk;
        pk.x = f2h2(o[0], o[1]);
        pk.y = f2h2(o[2], o[3]);
        pk.z = f2h2(o[4], o[5]);
        pk.w = f2h2(o[6], o[7]);
        *(uint4*)crow = pk;
    }
}

// -------------------- depthwise causal conv + bias + SiLU, L-tiled, fp16 ------
__device__ __forceinline__ float4 h4_to_f4(const __half* p) {
    uint2 v = *(const uint2*)p;
    float2 a = __half22float2(*(__half2*)&v.x);
    float2 b = __half22float2(*(__half2*)&v.y);
    return make_float4(a.x, a.y, b.x, b.y);
}

__global__ void __launch_bounds__(256) conv_silu_kernel(
    const __half* __restrict__ proj, const float* __restrict__ cw,
    const float* __restrict__ cb, __half* __restrict__ u)
{
    int idx = blockIdx.x * blockDim.x + threadIdx.x;
    if (idx >= (MROWS / 8) * (ISZ / 4)) return;
    int i4 = (idx & (ISZ / 4 - 1)) * 4;
    int rb = idx >> 7;
    int l0 = (rb & (LSEQ / 8 - 1)) * 8;
    size_t row0 = (size_t)rb * 8;

    float4 wr0 = ((const float4*)cw)[i4 + 0];
    float4 wr1 = ((const float4*)cw)[i4 + 1];
    float4 wr2 = ((const float4*)cw)[i4 + 2];
    float4 wr3 = ((const float4*)cw)[i4 + 3];
    float4 bias = *(const float4*)(cb + i4);

    float4 val[11];
#pragma unroll
    for (int j = 0; j < 11; j++) {
        int l = l0 + j - 3;
        if (l >= 0)
            val[j] = h4_to_f4(proj + (row0 + j - 3) * (2 * ISZ) + i4);
        else
            val[j] = make_float4(0.f, 0.f, 0.f, 0.f);
    }

#pragma unroll
    for (int k = 0; k < 8; k++) {
        float4 a;
        a.x = bias.x + wr0.w * val[k + 3].x + wr0.z * val[k + 2].x
                     + wr0.y * val[k + 1].x + wr0.x * val[k].x;
        a.y = bias.y + wr1.w * val[k + 3].y + wr1.z * val[k + 2].y
                     + wr1.y * val[k + 1].y + wr1.x * val[k].y;
        a.z = bias.z + wr2.w * val[k + 3].z + wr2.z * val[k + 2].z
                     + wr2.y * val[k + 1].z + wr2.x * val[k].z;
        a.w = bias.w + wr3.w * val[k + 3].w + wr3.z * val[k + 2].w
                     + wr3.y * val[k + 1].w + wr3.x * val[k].w;
        float4 o;
        o.x = a.x / (1.0f + __expf(-a.x));
        o.y = a.y / (1.0f + __expf(-a.y));
        o.z = a.z / (1.0f + __expf(-a.z));
        o.w = a.w / (1.0f + __expf(-a.w));
        uint2 pk;
        pk.x = f2h2(o.x, o.y);
        pk.y = f2h2(o.z, o.w);
        *(uint2*)(u + (row0 + k) * ISZ + i4) = pk;
    }
}

// -------------------- selective scan (fp16 dt/u/gate in, fp16 y out) ----------
__global__ void __launch_bounds__(256) scan_kernel(
    const __half* __restrict__ dt, const __half* __restrict__ u,
    const float* __restrict__ ssm, const __half* __restrict__ proj,
    const float* __restrict__ A_log, const float* __restrict__ Dp,
    __half* __restrict__ y)
{
    constexpr int CH = 64, TS = 32;
    __shared__ float sdt[TS][CH], su[TS][CH], sgate[TS][CH], sy[TS][CH];
    __shared__ float sB[TS][SSZ], sC[TS][SSZ];

    int b = blockIdx.y;
    int i0 = blockIdx.x * CH;
    int tid = threadIdx.x;
    int sg4 = tid & 3;
    int c = tid >> 2;
    int i = i0 + c;

    float Acoef[4];
#pragma unroll
    for (int j = 0; j < 4; j++) Acoef[j] = -__expf(A_log[i * SSZ + sg4 * 4 + j]);
    float Dv = Dp[i];
    float st[4] = {0.f, 0.f, 0.f, 0.f};

    for (int t0 = 0; t0 < LSEQ; t0 += TS) {
        // staged loads (half2-vectorized: 32 half2 per 64-channel row)
        for (int e = tid; e < TS * CH / 2; e += 256) {
            int t = e >> 5, c2 = e & 31;
            size_t r = (size_t)b * LSEQ + t0 + t;
            float2 fd = __half22float2(((const __half2*)(dt + r * ISZ + i0))[c2]);
            float2 fu = __half22float2(((const __half2*)(u + r * ISZ + i0))[c2]);
            float2 fg = __half22float2(
                ((const __half2*)(proj + r * (2 * ISZ) + ISZ + i0))[c2]);
            sdt[t][c2 * 2] = fd.x; sdt[t][c2 * 2 + 1] = fd.y;
            su[t][c2 * 2] = fu.x; su[t][c2 * 2 + 1] = fu.y;
            sgate[t][c2 * 2] = fg.x; sgate[t][c2 * 2 + 1] = fg.y;
        }
        for (int e = tid; e < TS * SSZ; e += 256) {
            int t = e / SSZ, s = e % SSZ;
            size_t r = (size_t)b * LSEQ + t0 + t;
            sB[t][s] = ssm[r * NSSM + RSZ + s];
            sC[t][s] = ssm[r * NSSM + RSZ + SSZ + s];
        }
        __syncthreads();

#pragma unroll 4
        for (int t = 0; t < TS; t++) {
            float dtv = sdt[t][c];
            float uv = su[t][c];
            float du = dtv * uv;
            float yp = 0.0f;
#pragma unroll
            for (int j = 0; j < 4; j++) {
                int s = sg4 * 4 + j;
                float dA = __expf(dtv * Acoef[j]);
                st[j] = dA * st[j] + du * sB[t][s];
                yp += st[j] * sC[t][s];
            }
            yp += __shfl_xor_sync(0xffffffffu, yp, 1);
            yp += __shfl_xor_sync(0xffffffffu, yp, 2);
            if (sg4 == 0) {
                float g = sgate[t][c];
                sy[t][c] = (yp + uv * Dv) * (g / (1.0f + __expf(-g)));
            }
        }
        __syncthreads();

        for (int e = tid; e < TS * CH / 2; e += 256) {
            int t = e >> 5, c2 = e & 31;
            size_t r = (size_t)b * LSEQ + t0 + t;
            ((__half2*)(y + r * ISZ + i0))[c2] =
                __floats2half2_rn(sy[t][c2 * 2], sy[t][c2 * 2 + 1]);
        }
        __syncthreads();
    }
}

// -------------------- host launcher --------------------
extern "C" void kernel_launch(void* const* d_in, const int* in_sizes, int n_in,
                              void* d_out, int out_size)
{
    (void)in_sizes; (void)n_in; (void)out_size;
    const float* x      = (const float*)d_in[0];
    const float* norm_w = (const float*)d_in[1];
    const float* in_w   = (const float*)d_in[2];
    const float* conv_w = (const float*)d_in[3];
    const float* conv_b = (const float*)d_in[4];
    const float* xp_w   = (const float*)d_in[5];
    const float* dt_w   = (const float*)d_in[6];
    const float* dt_b   = (const float*)d_in[7];
    const float* A_log  = (const float*)d_in[8];
    const float* Dp     = (const float*)d_in[9];
    const float* out_w  = (const float*)d_in[10];
    float* out = (float*)d_out;

    float* base = nullptr;
    cudaGetSymbolAddress((void**)&base, g_scratch);
    __half* h_buf  = (__half*)(base + OFF_H);
    __half* proj   = (__half*)(base + OFF_PROJ);
    __half* u_buf  = (__half*)(base + OFF_U);
    float*  ssm    = base + OFF_SSM;
    __half* dt_buf = (__half*)(base + OFF_DT);
    __half* y_buf  = (__half*)(base + OFF_Y);

    // residual stream lives in d_out; updated in place each layer
    cudaMemcpyAsync(out, x, sizeof(float) * (size_t)MROWS * Hh,
                    cudaMemcpyDeviceToDevice, 0);

    for (int li = 0; li < NLAY; li++) {
        const float* nw  = norm_w + (size_t)li * Hh;
        const float* iw  = in_w   + (size_t)li * 2 * ISZ * Hh;
        const float* cw  = conv_w + (size_t)li * ISZ * KC;
        const float* cb  = conv_b + (size_t)li * ISZ;
        const float* xpw = xp_w   + (size_t)li * NSSM * ISZ;
        const float* dtw = dt_w   + (size_t)li * ISZ * RSZ;
        const float* dtb = dt_b   + (size_t)li * ISZ;
        const float* al  = A_log  + (size_t)li * ISZ * SSZ;
        const float* dd  = Dp     + (size_t)li * ISZ;
        const float* ow  = out_w  + (size_t)li * Hh * ISZ;

        // 1) RMSNorm -> fp16 h
        rmsnorm_kernel<<<MROWS / 8, 256>>>(out, nw, h_buf);

        // 2) in_proj (fp16 TC, fp16 in/out)
        hgemm_kernel<EPI_NONE, true, true>
            <<<dim3(2 * ISZ / 128, MROWS / 128), 256>>>(
                h_buf, iw, proj, Hh, Hh, Hh, 2 * ISZ);

        // 3) depthwise causal conv + SiLU -> fp16 u (L-tiled)
        conv_silu_kernel<<<((MROWS / 8) * (ISZ / 4)) / 256, 256>>>(
            proj, cw, cb, u_buf);

        // 4) x_proj (fp16 TC): ssm[32768,48] = u @ xpw^T (fp32 out)
        hgemm48_kernel<<<dim3(1, MROWS / 128), 256>>>(
            u_buf, xpw, ssm, ISZ, ISZ, ISZ, NSSM);

        // 5) dt_proj + softplus (fp32 compute) -> fp16 dt
        gemm128_dt_kernel<<<dim3(ISZ / 128, MROWS / 128), 256>>>(
            ssm, dtw, dt_buf, RSZ, NSSM, RSZ, ISZ, dtb);

        // 6) selective scan (+ D-skip + gate) -> fp16 y
        scan_kernel<<<dim3(ISZ / 64, BATCH), 256>>>(
            dt_buf, u_buf, ssm, proj, al, dd, y_buf);

        // 7) out_proj + residual (fp16 TC, fp32 resadd into d_out)
        hgemm_kernel<EPI_RESADD, true, false>
            <<<dim3(Hh / 128, MROWS / 128), 256>>>(
                y_buf, ow, out, ISZ, ISZ, ISZ, Hh);
    }
}